// round 12
// baseline (speedup 1.0000x reference)
#include <cuda_runtime.h>
#include <cuda_bf16.h>
#include <cstdint>

// Problem constants
#define BB 2
#define NN 512
#define HH 128
#define DD 128
#define TT 8
#define ZZ 256
#define RET_ELEMS (BB*NN*DD)

// Scratch (device globals)
__device__ float g_A1[BB*NN*DD];      // m1 + mg + bm1 + bme          (by j)
__device__ float g_M2[BB*NN*DD];      // m2 + bm2                     (by i)
__device__ float g_O1[BB*NN*DD];      // z@Wo1 + bo1 + bo2            (by j)
__device__ float g_TTJ[BB*NN*TT];     // t1 + tg + bt1 + bte + btg    (by j)
__device__ float g_TTI[BB*NN*TT];     // t2 + bt2                     (by i)

// ---------------- smem layout (bytes) ----------------
enum : int {
    OFF_WH  = 0,                       // 34816 (17 n-atoms x 2 k-atoms)
    OFF_WL  = OFF_WH + 34*1024,        // 34816
    OFF_EH  = OFF_WL + 34*1024,        // 69632  (32KB)
    OFF_EL  = OFF_EH + 32*1024,        // 102400 (32KB)
    OFF_RAW = OFF_EL + 32*1024,        // 135168 (64KB: 128x128 fp32)
    OFF_ADJ = OFF_RAW + 64*1024,       // 200704 (512 fp32)
    OFF_A1  = OFF_ADJ + 2048,          // 202752 (136 fp32 + pad)
    OFF_ACC = OFF_A1 + 576,            // 203328 (4 x 128 fp32)
    SMEM_BYTES = OFF_ACC + 4*128*4     // 205376
};
#define DELTA_EL 32768
#define DELTA_WL 34816

#define SWZ(x) ((x) ^ (((x) >> 3) & 0x70))

__device__ __forceinline__ void cp16_to(uint32_t s, const float* g) {
    asm volatile("cp.async.cg.shared.global [%0], [%1], 16;" :: "r"(s), "l"(g));
}
__device__ __forceinline__ void ldsm4(uint32_t r[4], uint32_t addr) {
    asm volatile("ldmatrix.sync.aligned.m8n8.x4.shared.b16 {%0,%1,%2,%3}, [%4];"
        : "=r"(r[0]), "=r"(r[1]), "=r"(r[2]), "=r"(r[3]) : "r"(addr));
}
__device__ __forceinline__ void ldsm2(uint32_t r[2], uint32_t addr) {
    asm volatile("ldmatrix.sync.aligned.m8n8.x2.shared.b16 {%0,%1}, [%2];"
        : "=r"(r[0]), "=r"(r[1]) : "r"(addr));
}
__device__ __forceinline__ void mma_bf16(float d[4], const uint32_t a[4],
                                         uint32_t b0, uint32_t b1) {
    asm volatile("mma.sync.aligned.m16n8k16.row.col.f32.bf16.bf16.f32 "
        "{%0,%1,%2,%3}, {%4,%5,%6,%7}, {%8,%9}, {%0,%1,%2,%3};"
        : "+f"(d[0]), "+f"(d[1]), "+f"(d[2]), "+f"(d[3])
        : "r"(a[0]), "r"(a[1]), "r"(a[2]), "r"(a[3]), "r"(b0), "r"(b1));
}
// packed bf16x2 convert: element order {lo, hi} in the 32-bit word
__device__ __forceinline__ uint32_t bfpack2(float lo, float hi) {
    uint32_t r;
    asm("cvt.rn.bf16x2.f32 %0, %1, %2;" : "=r"(r) : "f"(hi), "f"(lo));
    return r;
}

// convert one float4 (row, k0) into swizzled bf16 hi/lo E tiles
__device__ __forceinline__ void cvt_store(char* ebH, int f, float4 v) {
    int row = f >> 5, k0 = (f & 31) * 4;
    uint32_t h01 = bfpack2(v.x, v.y);
    uint32_t h23 = bfpack2(v.z, v.w);
    float rx = v.x - __uint_as_float(h01 << 16);
    float ry = v.y - __uint_as_float(h01 & 0xffff0000u);
    float rz = v.z - __uint_as_float(h23 << 16);
    float rw = v.w - __uint_as_float(h23 & 0xffff0000u);
    uint32_t l01 = bfpack2(rx, ry);
    uint32_t l23 = bfpack2(rz, rw);
    uint32_t off = (uint32_t)(((row >> 3) + (k0 >> 6) * 16) * 1024 + (row & 7) * 128 + (k0 & 63) * 2);
    off = SWZ(off);
    *(uint2*)(ebH + off)            = make_uint2(h01, h23);
    *(uint2*)(ebH + DELTA_EL + off) = make_uint2(l01, l23);
}

// ---------------------------------------------------------------------------
// Kernel 1: per-node linears
// ---------------------------------------------------------------------------
__global__ __launch_bounds__(128) void setup_kernel(
    const float* __restrict__ node, const float* __restrict__ hidden,
    const float* __restrict__ graph,
    const float* __restrict__ Wm1, const float* __restrict__ bm1,
    const float* __restrict__ Wm2, const float* __restrict__ bm2,
    const float* __restrict__ bme,
    const float* __restrict__ Wmg, const float* __restrict__ bmg,
    const float* __restrict__ Wo1, const float* __restrict__ bo1,
    const float* __restrict__ bo2,
    const float* __restrict__ Wt1, const float* __restrict__ bt1,
    const float* __restrict__ Wt2, const float* __restrict__ bt2,
    const float* __restrict__ bte,
    const float* __restrict__ Wtg, const float* __restrict__ btg)
{
    __shared__ float Zs[8 * ZZ];
    __shared__ float Gs[HH];

    const int tid  = threadIdx.x;
    const int row0 = blockIdx.x * 8;
    const int b    = row0 / NN;
    const int m    = blockIdx.y;

    #pragma unroll
    for (int s = 0; s < 16; s++) {
        int idx = tid + 128 * s;
        int r = idx >> 8, k = idx & 255;
        Zs[idx] = (k < HH) ? node[(row0 + r) * HH + k]
                           : hidden[(row0 + r) * HH + (k - HH)];
    }
    if (tid < HH) Gs[tid] = graph[b * HH + tid];
    __syncthreads();

    if (m < 3) {
        const float* W = (m == 0) ? Wm1 : (m == 1) ? Wm2 : Wo1;
        const int d = tid;
        float acc[8];
        #pragma unroll
        for (int r = 0; r < 8; r++) acc[r] = 0.f;
        #pragma unroll 16
        for (int k = 0; k < ZZ; k++) {
            float w = W[k * DD + d];
            #pragma unroll
            for (int r = 0; r < 8; r++) acc[r] += Zs[r * ZZ + k] * w;
        }
        float cst;
        float* dst;
        if (m == 0) {
            float mgd = bmg[d];
            #pragma unroll 16
            for (int k = 0; k < HH; k++) mgd += Gs[k] * Wmg[k * DD + d];
            cst = bm1[d] + bme[d] + mgd;
            dst = g_A1;
        } else if (m == 1) { cst = bm2[d]; dst = g_M2; }
        else               { cst = bo1[d] + bo2[d]; dst = g_O1; }
        #pragma unroll
        for (int r = 0; r < 8; r++) dst[(row0 + r) * DD + d] = acc[r] + cst;
    } else {
        int r  = tid >> 4;
        int tt = tid & 15;
        if (tt < TT) {
            int t = tt;
            float tg = btg[t];
            for (int k = 0; k < HH; k++) tg += Gs[k] * Wtg[k * TT + t];
            float s = bt1[t] + bte[t] + tg;
            for (int k = 0; k < ZZ; k++) s += Zs[r * ZZ + k] * Wt1[k * TT + t];
            g_TTJ[(row0 + r) * TT + t] = s;
        } else {
            int t = tt - TT;
            float s = bt2[t];
            for (int k = 0; k < ZZ; k++) s += Zs[r * ZZ + k] * Wt2[k * TT + t];
            g_TTI[(row0 + r) * TT + t] = s;
        }
    }
}

// ---------------------------------------------------------------------------
// Kernel 2: HMMA bf16x3 edge GEMM, 512 threads = 16 warps (4 wm x 4 wn).
// Warp tile: 32 rows x 32 cols; wn==3 also owns the 8 triplet cols.
// cp.async raw staging (single buffer), serialized convert phase, E single.
// ---------------------------------------------------------------------------
__global__ __launch_bounds__(512, 1) void main_kernel(
    const float* __restrict__ edge, const float* __restrict__ adj,
    const float* __restrict__ Wme,  const float* __restrict__ Wte,
    const float* __restrict__ Wo2,  float* __restrict__ out)
{
    extern __shared__ __align__(1024) char smem[];
    const uint32_t sbase = (uint32_t)__cvta_generic_to_shared(smem);
    float* adjs = (float*)(smem + OFF_ADJ);
    float* a1s  = (float*)(smem + OFF_A1);
    float* accs = (float*)(smem + OFF_ACC);

    const int tid  = threadIdx.x;
    const int lane = tid & 31;
    const int wid  = tid >> 5;
    const int wm   = wid & 3;      // 32-row group
    const int wn   = wid >> 2;     // 32-col group (wn==3 also tri)
    const int bj   = blockIdx.x;
    const int b    = bj >> 9;
    const int j    = bj & 511;

    // ==================== prologue ====================
    // raw chunk 0 via cp.async (non-blocking)
    #pragma unroll
    for (int s = 0; s < 8; s++) {
        int f = tid + 512 * s;
        int row = f >> 5, kq = f & 31;
        cp16_to(sbase + OFF_RAW + f * 16,
                edge + ((size_t)((b * NN + row) * NN + j)) * HH + kq * 4);
    }
    asm volatile("cp.async.commit_group;" ::: "memory");

    // stage W = [Wme | Wte] bf16 hi/lo (blocked-atom SW128)
    for (int idx = tid; idx < 136 * 128; idx += 512) {
        int n = idx % 136;
        int k = idx / 136;
        float w = (n < DD) ? Wme[k * DD + n] : Wte[k * TT + (n - DD)];
        __nv_bfloat16 h = __float2bfloat16(w);
        __nv_bfloat16 l = __float2bfloat16(w - __bfloat162float(h));
        uint32_t off = (uint32_t)(((n >> 3) + (k >> 6) * 17) * 1024 + (n & 7) * 128 + (k & 63) * 2);
        off = SWZ(off);
        *(__nv_bfloat16*)(smem + OFF_WH + off) = h;
        *(__nv_bfloat16*)(smem + OFF_WL + off) = l;
    }
    if (tid < DD)       a1s[tid] = g_A1[bj * DD + tid];
    else if (tid < 136) a1s[tid] = g_TTJ[bj * TT + (tid - DD)];
    // full adjacency column (512 senders)
    adjs[tid] = adj[(size_t)(b * NN + tid) * NN + j];

    asm volatile("cp.async.wait_group 0;" ::: "memory");
    __syncthreads();

    // ---- per-lane address constants ----
    const int a_rin = lane & 15;
    const uint32_t a_kg2 = (uint32_t)((lane >> 4) * 16);
    uint32_t linA0, linA1, maskA;
    {
        int r0 = wm * 32 + a_rin;
        int r1 = r0 + 16;
        linA0 = (uint32_t)(OFF_EH + (r0 >> 3) * 1024 + (r0 & 7) * 128);
        linA1 = (uint32_t)(OFF_EH + (r1 >> 3) * 1024 + (r1 & 7) * 128);
        maskA = (uint32_t)((r0 & 7) << 4);
    }
    const int b_rin = lane & 7;
    const uint32_t b_kg2 = (uint32_t)(((lane >> 3) & 1) * 16);
    uint32_t linB, maskB, linBt;
    {
        int n0 = wn * 32 + (lane >> 4) * 8 + b_rin;
        linB  = (uint32_t)(OFF_WH + (n0 >> 3) * 1024 + (n0 & 7) * 128);
        maskB = (uint32_t)(b_rin << 4);
        linBt = (uint32_t)(OFF_WH + 16 * 1024 + b_rin * 128);
    }

    float cmax[4][2];
    #pragma unroll
    for (int nt = 0; nt < 4; nt++) { cmax[nt][0] = -3.402823466e38f; cmax[nt][1] = -3.402823466e38f; }

    const float4* rawf4 = (const float4*)(smem + OFF_RAW);
    float d[2][5][4];   // [mt][nt 0..3 msg, 4 tri(wn==3)][frag]

    for (int c = 0; c < 4; c++) {
        const int i0 = c * 128;

        // ---- convert phase: raw fp32 -> E hi/lo (serialized, cheap) ----
        {
            char* ebH = smem + OFF_EH;
            #pragma unroll
            for (int s = 0; s < 8; s++) {
                int f = tid + 512 * s;
                cvt_store(ebH, f, rawf4[f]);
            }
        }
        __syncthreads();   // raw consumed, E ready

        // ---- issue cp.async for chunk c+1 (streams during MMA) ----
        if (c < 3) {
            const int i1 = i0 + 128;
            #pragma unroll
            for (int s = 0; s < 8; s++) {
                int f = tid + 512 * s;
                int row = f >> 5, kq = f & 31;
                cp16_to(sbase + OFF_RAW + f * 16,
                        edge + ((size_t)((b * NN + i1 + row) * NN + j)) * HH + kq * 4);
            }
            asm volatile("cp.async.commit_group;" ::: "memory");
        }

        // ---- MMA mainloop ----
        #pragma unroll
        for (int mt = 0; mt < 2; mt++)
            #pragma unroll
            for (int nt = 0; nt < 5; nt++)
                #pragma unroll
                for (int q = 0; q < 4; q++) d[mt][nt][q] = 0.f;

        #pragma unroll
        for (int ks = 0; ks < 8; ks++) {
            const uint32_t kofA = (uint32_t)((ks & 3) * 32) + a_kg2;
            const uint32_t kofB = (uint32_t)((ks & 3) * 32) + b_kg2;
            const uint32_t ksa  = (uint32_t)((ks >> 2) * 16384);
            const uint32_t ksb  = (uint32_t)((ks >> 2) * 17408);

            uint32_t ah[2][4], al[2][4];
            {
                uint32_t ad0 = sbase + (((linA0 + kofA) ^ maskA) + ksa);
                uint32_t ad1 = sbase + (((linA1 + kofA) ^ maskA) + ksa);
                ldsm4(ah[0], ad0);
                ldsm4(al[0], ad0 + DELTA_EL);
                ldsm4(ah[1], ad1);
                ldsm4(al[1], ad1 + DELTA_EL);
            }
            uint32_t bh[2][4], bl[2][4];
            #pragma unroll
            for (int p = 0; p < 2; p++) {
                uint32_t bd = sbase + (((linB + (uint32_t)(p * 2048) + kofB) ^ maskB) + ksb);
                ldsm4(bh[p], bd);
                ldsm4(bl[p], bd + DELTA_WL);
            }
            uint32_t th[2], tl[2];
            if (wn == 3) {
                uint32_t bt = sbase + (((linBt + kofB) ^ maskB) + ksb);
                ldsm2(th, bt);
                ldsm2(tl, bt + DELTA_WL);
            }

            // hh
            #pragma unroll
            for (int p = 0; p < 2; p++)
                #pragma unroll
                for (int mt = 0; mt < 2; mt++) {
                    mma_bf16(d[mt][2*p],   ah[mt], bh[p][0], bh[p][1]);
                    mma_bf16(d[mt][2*p+1], ah[mt], bh[p][2], bh[p][3]);
                }
            if (wn == 3) { mma_bf16(d[0][4], ah[0], th[0], th[1]); mma_bf16(d[1][4], ah[1], th[0], th[1]); }
            // hl
            #pragma unroll
            for (int p = 0; p < 2; p++)
                #pragma unroll
                for (int mt = 0; mt < 2; mt++) {
                    mma_bf16(d[mt][2*p],   ah[mt], bl[p][0], bl[p][1]);
                    mma_bf16(d[mt][2*p+1], ah[mt], bl[p][2], bl[p][3]);
                }
            if (wn == 3) { mma_bf16(d[0][4], ah[0], tl[0], tl[1]); mma_bf16(d[1][4], ah[1], tl[0], tl[1]); }
            // lh
            #pragma unroll
            for (int p = 0; p < 2; p++)
                #pragma unroll
                for (int mt = 0; mt < 2; mt++) {
                    mma_bf16(d[mt][2*p],   al[mt], bh[p][0], bh[p][1]);
                    mma_bf16(d[mt][2*p+1], al[mt], bh[p][2], bh[p][3]);
                }
            if (wn == 3) { mma_bf16(d[0][4], al[0], th[0], th[1]); mma_bf16(d[1][4], al[1], th[0], th[1]); }
        }

        // ---- epilogue: mask + running max; triplet relu + store ----
        {
            const int r0e   = lane >> 2;
            const int cpair = (lane & 3) * 2;
            #pragma unroll
            for (int mt = 0; mt < 2; mt++) {
                const int rloc = wm * 32 + mt * 16 + r0e;
                const int ilo  = i0 + rloc;
                const int ihi  = ilo + 8;
                const float alo  = adjs[ilo];
                const float ahiv = adjs[ihi];
                const float* m2lo = &g_M2[(size_t)(b * NN + ilo) * DD];
                const float* m2hi = &g_M2[(size_t)(b * NN + ihi) * DD];
                #pragma unroll
                for (int nt = 0; nt < 4; nt++) {
                    const int col = wn * 32 + nt * 8 + cpair;
                    float2 a1v = *(const float2*)&a1s[col];
                    float2 vlo = *(const float2*)&m2lo[col];
                    float2 vhi = *(const float2*)&m2hi[col];
                    cmax[nt][0] = fmaxf(cmax[nt][0], alo  * (d[mt][nt][0] + a1v.x + vlo.x));
                    cmax[nt][1] = fmaxf(cmax[nt][1], alo  * (d[mt][nt][1] + a1v.y + vlo.y));
                    cmax[nt][0] = fmaxf(cmax[nt][0], ahiv * (d[mt][nt][2] + a1v.x + vhi.x));
                    cmax[nt][1] = fmaxf(cmax[nt][1], ahiv * (d[mt][nt][3] + a1v.y + vhi.y));
                }
                if (wn == 3) {
                    float2 tj  = *(const float2*)&a1s[128 + cpair];
                    float2 tlo = *(const float2*)&g_TTI[(size_t)(b * NN + ilo) * TT + cpair];
                    float2 thi = *(const float2*)&g_TTI[(size_t)(b * NN + ihi) * TT + cpair];
                    float2 o0, o1;
                    o0.x = fmaxf(d[mt][4][0] + tj.x + tlo.x, 0.f);
                    o0.y = fmaxf(d[mt][4][1] + tj.y + tlo.y, 0.f);
                    o1.x = fmaxf(d[mt][4][2] + tj.x + thi.x, 0.f);
                    o1.y = fmaxf(d[mt][4][3] + tj.y + thi.y, 0.f);
                    *(float2*)&out[RET_ELEMS + ((size_t)(b * NN + ilo) * NN + j) * TT + cpair] = o0;
                    *(float2*)&out[RET_ELEMS + ((size_t)(b * NN + ihi) * NN + j) * TT + cpair] = o1;
                }
            }
        }

        if (c < 3) asm volatile("cp.async.wait_group 0;" ::: "memory");
        __syncthreads();   // MMA done reading E; raw(c+1) landed
    }

    // ---- combine maxes: shfl over rows, cross-warp via smem ----
    #pragma unroll
    for (int nt = 0; nt < 4; nt++) {
        #pragma unroll
        for (int q = 0; q < 2; q++) {
            float v = cmax[nt][q];
            v = fmaxf(v, __shfl_xor_sync(0xffffffffu, v, 4));
            v = fmaxf(v, __shfl_xor_sync(0xffffffffu, v, 8));
            v = fmaxf(v, __shfl_xor_sync(0xffffffffu, v, 16));
            cmax[nt][q] = v;
        }
    }
    if (lane < 4) {
        #pragma unroll
        for (int nt = 0; nt < 4; nt++) {
            int col = wn * 32 + nt * 8 + lane * 2;
            accs[wm * 128 + col]     = cmax[nt][0];
            accs[wm * 128 + col + 1] = cmax[nt][1];
        }
    }
    __syncthreads();

    // ---- final: combine 4 wm groups, ret GEMM ----
    float* msgs = a1s;
    if (tid < DD) {
        float m = accs[tid];
        #pragma unroll
        for (int g = 1; g < 4; g++) m = fmaxf(m, accs[g * 128 + tid]);
        msgs[tid] = m;
    }
    __syncthreads();
    if (tid < DD) {
        float r = g_O1[bj * DD + tid];
        #pragma unroll 8
        for (int k = 0; k < DD; k++) r += msgs[k] * Wo2[k * DD + tid];
        out[bj * DD + tid] = r;
    }
}

// ---------------------------------------------------------------------------
extern "C" void kernel_launch(void* const* d_in, const int* in_sizes, int n_in,
                              void* d_out, int out_size)
{
    const float* node   = (const float*)d_in[0];
    const float* edge   = (const float*)d_in[1];
    const float* graph  = (const float*)d_in[2];
    const float* adj    = (const float*)d_in[3];
    const float* hidden = (const float*)d_in[4];
    const float* Wm1 = (const float*)d_in[5];  const float* bm1 = (const float*)d_in[6];
    const float* Wm2 = (const float*)d_in[7];  const float* bm2 = (const float*)d_in[8];
    const float* Wme = (const float*)d_in[9];  const float* bme = (const float*)d_in[10];
    const float* Wmg = (const float*)d_in[11]; const float* bmg = (const float*)d_in[12];
    const float* Wo1 = (const float*)d_in[13]; const float* bo1 = (const float*)d_in[14];
    const float* Wo2 = (const float*)d_in[15]; const float* bo2 = (const float*)d_in[16];
    const float* Wt1 = (const float*)d_in[17]; const float* bt1 = (const float*)d_in[18];
    const float* Wt2 = (const float*)d_in[19]; const float* bt2 = (const float*)d_in[20];
    const float* Wte = (const float*)d_in[21]; const float* bte = (const float*)d_in[22];
    const float* Wtg = (const float*)d_in[23]; const float* btg = (const float*)d_in[24];

    float* out = (float*)d_out;

    cudaFuncSetAttribute(main_kernel, cudaFuncAttributeMaxDynamicSharedMemorySize,
                         SMEM_BYTES);

    setup_kernel<<<dim3(128, 4), 128>>>(node, hidden, graph,
                                        Wm1, bm1, Wm2, bm2, bme, Wmg, bmg,
                                        Wo1, bo1, bo2,
                                        Wt1, bt1, Wt2, bt2, bte, Wtg, btg);

    main_kernel<<<BB * NN, 512, SMEM_BYTES>>>(edge, adj, Wme, Wte, Wo2, out);
}

// round 16
// speedup vs baseline: 1.5456x; 1.5456x over previous
#include <cuda_runtime.h>
#include <cuda_fp16.h>
#include <cstdint>

// Problem constants
#define BB 2
#define NN 512
#define HH 128
#define DD 128
#define TT 8
#define ZZ 256
#define RET_ELEMS (BB*NN*DD)

// Scratch (device globals)
__device__ float g_A1[BB*NN*DD];      // m1 + mg + bm1 + bme          (by j)
__device__ float g_M2[BB*NN*DD];      // m2 + bm2                     (by i)
__device__ float g_O1[BB*NN*DD];      // z@Wo1 + bo1 + bo2            (by j)
__device__ float g_TTJ[BB*NN*TT];     // t1 + tg + bt1 + bte + btg    (by j)
__device__ float g_TTI[BB*NN*TT];     // t2 + bt2                     (by i)

// ---------------- smem layout (bytes) ----------------
enum : int {
    OFF_WH  = 0,                       // 34816 (17 n-atoms x 2 k-atoms)
    OFF_WL  = OFF_WH + 34*1024,        // 34816
    OFF_EH  = OFF_WL + 34*1024,        // 69632  (32KB, fp16 single)
    OFF_RAW = OFF_EH + 32*1024,        // 102400 (64KB: 128x128 fp32)
    OFF_ADJ = OFF_RAW + 64*1024,       // 167936 (512 fp32)
    OFF_A1  = OFF_ADJ + 2048,          // 169984 (136 fp32 + pad)
    OFF_ACC = OFF_A1 + 576,            // 170560 (8 x 128 fp32)
    SMEM_BYTES = OFF_ACC + 8*128*4     // 174656
};
#define DELTA_WL 34816

#define SWZ(x) ((x) ^ (((x) >> 3) & 0x70))

__device__ __forceinline__ void cp16_to(uint32_t s, const float* g) {
    asm volatile("cp.async.cg.shared.global [%0], [%1], 16;" :: "r"(s), "l"(g));
}
__device__ __forceinline__ void ldsm4(uint32_t r[4], uint32_t addr) {
    asm volatile("ldmatrix.sync.aligned.m8n8.x4.shared.b16 {%0,%1,%2,%3}, [%4];"
        : "=r"(r[0]), "=r"(r[1]), "=r"(r[2]), "=r"(r[3]) : "r"(addr));
}
__device__ __forceinline__ void ldsm2(uint32_t r[2], uint32_t addr) {
    asm volatile("ldmatrix.sync.aligned.m8n8.x2.shared.b16 {%0,%1}, [%2];"
        : "=r"(r[0]), "=r"(r[1]) : "r"(addr));
}
__device__ __forceinline__ void mma_f16(float d[4], const uint32_t a[4],
                                        uint32_t b0, uint32_t b1) {
    asm volatile("mma.sync.aligned.m16n8k16.row.col.f32.f16.f16.f32 "
        "{%0,%1,%2,%3}, {%4,%5,%6,%7}, {%8,%9}, {%0,%1,%2,%3};"
        : "+f"(d[0]), "+f"(d[1]), "+f"(d[2]), "+f"(d[3])
        : "r"(a[0]), "r"(a[1]), "r"(a[2]), "r"(a[3]), "r"(b0), "r"(b1));
}
// packed fp16x2 convert: element order {lo, hi} in the 32-bit word
__device__ __forceinline__ uint32_t hfpack2(float lo, float hi) {
    uint32_t r;
    asm("cvt.rn.f16x2.f32 %0, %1, %2;" : "=r"(r) : "f"(hi), "f"(lo));
    return r;
}

// convert one float4 (row, k0) into swizzled fp16 E tile (hi only)
__device__ __forceinline__ void cvt_store(char* ebH, int f, float4 v) {
    int row = f >> 5, k0 = (f & 31) * 4;
    uint32_t h01 = hfpack2(v.x, v.y);
    uint32_t h23 = hfpack2(v.z, v.w);
    uint32_t off = (uint32_t)(((row >> 3) + (k0 >> 6) * 16) * 1024 + (row & 7) * 128 + (k0 & 63) * 2);
    off = SWZ(off);
    *(uint2*)(ebH + off) = make_uint2(h01, h23);
}

// ---------------------------------------------------------------------------
// Kernel 1: per-node linears
// ---------------------------------------------------------------------------
__global__ __launch_bounds__(128) void setup_kernel(
    const float* __restrict__ node, const float* __restrict__ hidden,
    const float* __restrict__ graph,
    const float* __restrict__ Wm1, const float* __restrict__ bm1,
    const float* __restrict__ Wm2, const float* __restrict__ bm2,
    const float* __restrict__ bme,
    const float* __restrict__ Wmg, const float* __restrict__ bmg,
    const float* __restrict__ Wo1, const float* __restrict__ bo1,
    const float* __restrict__ bo2,
    const float* __restrict__ Wt1, const float* __restrict__ bt1,
    const float* __restrict__ Wt2, const float* __restrict__ bt2,
    const float* __restrict__ bte,
    const float* __restrict__ Wtg, const float* __restrict__ btg)
{
    __shared__ float Zs[8 * ZZ];
    __shared__ float Gs[HH];

    const int tid  = threadIdx.x;
    const int row0 = blockIdx.x * 8;
    const int b    = row0 / NN;
    const int m    = blockIdx.y;

    #pragma unroll
    for (int s = 0; s < 16; s++) {
        int idx = tid + 128 * s;
        int r = idx >> 8, k = idx & 255;
        Zs[idx] = (k < HH) ? node[(row0 + r) * HH + k]
                           : hidden[(row0 + r) * HH + (k - HH)];
    }
    if (tid < HH) Gs[tid] = graph[b * HH + tid];
    __syncthreads();

    if (m < 3) {
        const float* W = (m == 0) ? Wm1 : (m == 1) ? Wm2 : Wo1;
        const int d = tid;
        float acc[8];
        #pragma unroll
        for (int r = 0; r < 8; r++) acc[r] = 0.f;
        #pragma unroll 16
        for (int k = 0; k < ZZ; k++) {
            float w = W[k * DD + d];
            #pragma unroll
            for (int r = 0; r < 8; r++) acc[r] += Zs[r * ZZ + k] * w;
        }
        float cst;
        float* dst;
        if (m == 0) {
            float mgd = bmg[d];
            #pragma unroll 16
            for (int k = 0; k < HH; k++) mgd += Gs[k] * Wmg[k * DD + d];
            cst = bm1[d] + bme[d] + mgd;
            dst = g_A1;
        } else if (m == 1) { cst = bm2[d]; dst = g_M2; }
        else               { cst = bo1[d] + bo2[d]; dst = g_O1; }
        #pragma unroll
        for (int r = 0; r < 8; r++) dst[(row0 + r) * DD + d] = acc[r] + cst;
    } else {
        int r  = tid >> 4;
        int tt = tid & 15;
        if (tt < TT) {
            int t = tt;
            float tg = btg[t];
            for (int k = 0; k < HH; k++) tg += Gs[k] * Wtg[k * TT + t];
            float s = bt1[t] + bte[t] + tg;
            for (int k = 0; k < ZZ; k++) s += Zs[r * ZZ + k] * Wt1[k * TT + t];
            g_TTJ[(row0 + r) * TT + t] = s;
        } else {
            int t = tt - TT;
            float s = bt2[t];
            for (int k = 0; k < ZZ; k++) s += Zs[r * ZZ + k] * Wt2[k * TT + t];
            g_TTI[(row0 + r) * TT + t] = s;
        }
    }
}

// ---------------------------------------------------------------------------
// Kernel 2: HMMA fp16 2-split edge GEMM. 512 threads = 16 warps:
// wm = wid&7 (16 rows), wn = wid>>3 (64 cols; wn==1 also owns 8 tri cols).
// W split exact (wh+wl fp16), E rounded once to fp16 -> 2 MMA terms.
// Structure identical to the R6 winner (cp.async raw staging, serialized
// convert, prefetch during MMA).
// ---------------------------------------------------------------------------
__global__ __launch_bounds__(512, 1) void main_kernel(
    const float* __restrict__ edge, const float* __restrict__ adj,
    const float* __restrict__ Wme,  const float* __restrict__ Wte,
    const float* __restrict__ Wo2,  float* __restrict__ out)
{
    extern __shared__ __align__(1024) char smem[];
    const uint32_t sbase = (uint32_t)__cvta_generic_to_shared(smem);
    float* adjs = (float*)(smem + OFF_ADJ);
    float* a1s  = (float*)(smem + OFF_A1);
    float* accs = (float*)(smem + OFF_ACC);

    const int tid  = threadIdx.x;
    const int lane = tid & 31;
    const int wid  = tid >> 5;
    const int wm   = wid & 7;      // 16-row group
    const int wn   = wid >> 3;     // 64-col group (wn==1 also tri)
    const int bj   = blockIdx.x;
    const int b    = bj >> 9;
    const int j    = bj & 511;

    // ==================== prologue ====================
    // raw chunk 0 via cp.async (non-blocking)
    #pragma unroll
    for (int s = 0; s < 8; s++) {
        int f = tid + 512 * s;
        int row = f >> 5, kq = f & 31;
        cp16_to(sbase + OFF_RAW + f * 16,
                edge + ((size_t)((b * NN + row) * NN + j)) * HH + kq * 4);
    }
    asm volatile("cp.async.commit_group;" ::: "memory");

    // stage W = [Wme | Wte] fp16 hi/lo (blocked-atom SW128); hi+lo is exact
    for (int idx = tid; idx < 136 * 128; idx += 512) {
        int n = idx % 136;
        int k = idx / 136;
        float w = (n < DD) ? Wme[k * DD + n] : Wte[k * TT + (n - DD)];
        __half h = __float2half_rn(w);
        __half l = __float2half_rn(w - __half2float(h));
        uint32_t off = (uint32_t)(((n >> 3) + (k >> 6) * 17) * 1024 + (n & 7) * 128 + (k & 63) * 2);
        off = SWZ(off);
        *(__half*)(smem + OFF_WH + off) = h;
        *(__half*)(smem + OFF_WL + off) = l;
    }
    if (tid < DD)       a1s[tid] = g_A1[bj * DD + tid];
    else if (tid < 136) a1s[tid] = g_TTJ[bj * TT + (tid - DD)];
    // full adjacency column (512 senders)
    adjs[tid] = adj[(size_t)(b * NN + tid) * NN + j];

    asm volatile("cp.async.wait_group 0;" ::: "memory");
    __syncthreads();

    // ---- per-lane address constants ----
    const int a_rin = lane & 15;
    const uint32_t a_kg2 = (uint32_t)((lane >> 4) * 16);
    uint32_t linA, maskA;
    {
        int r0 = wm * 16 + a_rin;
        linA  = (uint32_t)(OFF_EH + (r0 >> 3) * 1024 + (r0 & 7) * 128);
        maskA = (uint32_t)((r0 & 7) << 4);
    }
    const int b_rin = lane & 7;
    const uint32_t b_kg2 = (uint32_t)(((lane >> 3) & 1) * 16);
    uint32_t linB, maskB, linBt;
    {
        int n0 = wn * 64 + (lane >> 4) * 8 + b_rin;
        linB  = (uint32_t)(OFF_WH + (n0 >> 3) * 1024 + (n0 & 7) * 128);
        maskB = (uint32_t)(b_rin << 4);
        linBt = (uint32_t)(OFF_WH + 16 * 1024 + b_rin * 128);
    }

    float cmax[8][2];
    #pragma unroll
    for (int nt = 0; nt < 8; nt++) { cmax[nt][0] = -3.402823466e38f; cmax[nt][1] = -3.402823466e38f; }

    const float4* rawf4 = (const float4*)(smem + OFF_RAW);
    float d[9][4];   // nt 0..7 msg cols, 8 = tri (wn==1)

    for (int c = 0; c < 4; c++) {
        const int i0 = c * 128;

        // ---- convert phase: raw fp32 -> E fp16 (hi only) ----
        {
            char* ebH = smem + OFF_EH;
            #pragma unroll
            for (int s = 0; s < 8; s++) {
                int f = tid + 512 * s;
                cvt_store(ebH, f, rawf4[f]);
            }
        }
        __syncthreads();   // raw consumed, E ready

        // ---- issue cp.async for chunk c+1 (streams during MMA) ----
        if (c < 3) {
            const int i1 = i0 + 128;
            #pragma unroll
            for (int s = 0; s < 8; s++) {
                int f = tid + 512 * s;
                int row = f >> 5, kq = f & 31;
                cp16_to(sbase + OFF_RAW + f * 16,
                        edge + ((size_t)((b * NN + i1 + row) * NN + j)) * HH + kq * 4);
            }
            asm volatile("cp.async.commit_group;" ::: "memory");
        }

        // ---- MMA mainloop: 2-term fp16 split ----
        #pragma unroll
        for (int nt = 0; nt < 9; nt++)
            #pragma unroll
            for (int q = 0; q < 4; q++) d[nt][q] = 0.f;

        #pragma unroll
        for (int ks = 0; ks < 8; ks++) {
            const uint32_t kofA = (uint32_t)((ks & 3) * 32) + a_kg2;
            const uint32_t kofB = (uint32_t)((ks & 3) * 32) + b_kg2;
            const uint32_t ksa  = (uint32_t)((ks >> 2) * 16384);
            const uint32_t ksb  = (uint32_t)((ks >> 2) * 17408);

            uint32_t ah[4];
            ldsm4(ah, sbase + (((linA + kofA) ^ maskA) + ksa));

            uint32_t bh[4][4], bl[4][4];
            #pragma unroll
            for (int p = 0; p < 4; p++) {
                uint32_t bd = sbase + (((linB + (uint32_t)(p * 2048) + kofB) ^ maskB) + ksb);
                ldsm4(bh[p], bd);
                ldsm4(bl[p], bd + DELTA_WL);
            }
            uint32_t th[2], tl[2];
            if (wn) {
                uint32_t bt = sbase + (((linBt + kofB) ^ maskB) + ksb);
                ldsm2(th, bt);
                ldsm2(tl, bt + DELTA_WL);
            }

            // hi term
            #pragma unroll
            for (int p = 0; p < 4; p++) {
                mma_f16(d[2*p],   ah, bh[p][0], bh[p][1]);
                mma_f16(d[2*p+1], ah, bh[p][2], bh[p][3]);
            }
            if (wn) mma_f16(d[8], ah, th[0], th[1]);
            // lo term
            #pragma unroll
            for (int p = 0; p < 4; p++) {
                mma_f16(d[2*p],   ah, bl[p][0], bl[p][1]);
                mma_f16(d[2*p+1], ah, bl[p][2], bl[p][3]);
            }
            if (wn) mma_f16(d[8], ah, tl[0], tl[1]);
        }

        // ---- epilogue: mask + running max; triplet relu + store ----
        {
            const int r0e   = lane >> 2;
            const int cpair = (lane & 3) * 2;
            const int rloc  = wm * 16 + r0e;
            const int ilo   = i0 + rloc;
            const int ihi   = ilo + 8;
            const float alo  = adjs[ilo];
            const float ahiv = adjs[ihi];
            const float* m2lo = &g_M2[(size_t)(b * NN + ilo) * DD];
            const float* m2hi = &g_M2[(size_t)(b * NN + ihi) * DD];
            #pragma unroll
            for (int nt = 0; nt < 8; nt++) {
                const int col = wn * 64 + nt * 8 + cpair;
                float2 a1v = *(const float2*)&a1s[col];
                float2 vlo = *(const float2*)&m2lo[col];
                float2 vhi = *(const float2*)&m2hi[col];
                cmax[nt][0] = fmaxf(cmax[nt][0], alo  * (d[nt][0] + a1v.x + vlo.x));
                cmax[nt][1] = fmaxf(cmax[nt][1], alo  * (d[nt][1] + a1v.y + vlo.y));
                cmax[nt][0] = fmaxf(cmax[nt][0], ahiv * (d[nt][2] + a1v.x + vhi.x));
                cmax[nt][1] = fmaxf(cmax[nt][1], ahiv * (d[nt][3] + a1v.y + vhi.y));
            }
            if (wn) {
                float2 tj  = *(const float2*)&a1s[128 + cpair];
                float2 tlo = *(const float2*)&g_TTI[(size_t)(b * NN + ilo) * TT + cpair];
                float2 thi = *(const float2*)&g_TTI[(size_t)(b * NN + ihi) * TT + cpair];
                float2 o0, o1;
                o0.x = fmaxf(d[8][0] + tj.x + tlo.x, 0.f);
                o0.y = fmaxf(d[8][1] + tj.y + tlo.y, 0.f);
                o1.x = fmaxf(d[8][2] + tj.x + thi.x, 0.f);
                o1.y = fmaxf(d[8][3] + tj.y + thi.y, 0.f);
                *(float2*)&out[RET_ELEMS + ((size_t)(b * NN + ilo) * NN + j) * TT + cpair] = o0;
                *(float2*)&out[RET_ELEMS + ((size_t)(b * NN + ihi) * NN + j) * TT + cpair] = o1;
            }
        }

        if (c < 3) asm volatile("cp.async.wait_group 0;" ::: "memory");
        __syncthreads();   // MMA done reading E; raw(c+1) landed
    }

    // ---- combine maxes: shfl over rows, cross-warp via smem ----
    #pragma unroll
    for (int nt = 0; nt < 8; nt++) {
        #pragma unroll
        for (int q = 0; q < 2; q++) {
            float v = cmax[nt][q];
            v = fmaxf(v, __shfl_xor_sync(0xffffffffu, v, 4));
            v = fmaxf(v, __shfl_xor_sync(0xffffffffu, v, 8));
            v = fmaxf(v, __shfl_xor_sync(0xffffffffu, v, 16));
            cmax[nt][q] = v;
        }
    }
    if (lane < 4) {
        #pragma unroll
        for (int nt = 0; nt < 8; nt++) {
            int col = wn * 64 + nt * 8 + lane * 2;
            accs[wm * 128 + col]     = cmax[nt][0];
            accs[wm * 128 + col + 1] = cmax[nt][1];
        }
    }
    __syncthreads();

    // ---- final: combine 8 wm groups, ret GEMM ----
    float* msgs = a1s;
    if (tid < DD) {
        float m = accs[tid];
        #pragma unroll
        for (int g = 1; g < 8; g++) m = fmaxf(m, accs[g * 128 + tid]);
        msgs[tid] = m;
    }
    __syncthreads();
    if (tid < DD) {
        float r = g_O1[bj * DD + tid];
        #pragma unroll 8
        for (int k = 0; k < DD; k++) r += msgs[k] * Wo2[k * DD + tid];
        out[bj * DD + tid] = r;
    }
}

// ---------------------------------------------------------------------------
extern "C" void kernel_launch(void* const* d_in, const int* in_sizes, int n_in,
                              void* d_out, int out_size)
{
    const float* node   = (const float*)d_in[0];
    const float* edge   = (const float*)d_in[1];
    const float* graph  = (const float*)d_in[2];
    const float* adj    = (const float*)d_in[3];
    const float* hidden = (const float*)d_in[4];
    const float* Wm1 = (const float*)d_in[5];  const float* bm1 = (const float*)d_in[6];
    const float* Wm2 = (const float*)d_in[7];  const float* bm2 = (const float*)d_in[8];
    const float* Wme = (const float*)d_in[9];  const float* bme = (const float*)d_in[10];
    const float* Wmg = (const float*)d_in[11]; const float* bmg = (const float*)d_in[12];
    const float* Wo1 = (const float*)d_in[13]; const float* bo1 = (const float*)d_in[14];
    const float* Wo2 = (const float*)d_in[15]; const float* bo2 = (const float*)d_in[16];
    const float* Wt1 = (const float*)d_in[17]; const float* bt1 = (const float*)d_in[18];
    const float* Wt2 = (const float*)d_in[19]; const float* bt2 = (const float*)d_in[20];
    const float* Wte = (const float*)d_in[21]; const float* bte = (const float*)d_in[22];
    const float* Wtg = (const float*)d_in[23]; const float* btg = (const float*)d_in[24];

    float* out = (float*)d_out;

    cudaFuncSetAttribute(main_kernel, cudaFuncAttributeMaxDynamicSharedMemorySize,
                         SMEM_BYTES);

    setup_kernel<<<dim3(128, 4), 128>>>(node, hidden, graph,
                                        Wm1, bm1, Wm2, bm2, bme, Wmg, bmg,
                                        Wo1, bo1, bo2,
                                        Wt1, bt1, Wt2, bt2, bte, Wtg, btg);

    main_kernel<<<BB * NN, 512, SMEM_BYTES>>>(edge, adj, Wme, Wte, Wo2, out);
}